// round 11
// baseline (speedup 1.0000x reference)
#include <cuda_runtime.h>
#include <cstdint>

// Problem constants (shapes fixed by setup_inputs)
#define N_IMG   32
#define C_DIM   512
#define HW      64
#define N_DB    400000
#define L_REP   100
#define T_OUT   80
#define VOCAB   5000

// Main-GEMM tiling
#define TN      256      // candidate rows per CTA
#define KC      32       // K-chunk (floats) staged per iteration
#define BPITCH  36       // padded smem row pitch (conflict-free frag loads)
#define NBLK    ((N_DB + TN - 1) / TN)   // 1563
#define EPS_D   0.02f    // candidate margin in distance units (~28x tf32 error)

#define ONE_HOT_ELEMS (N_IMG * T_OUT * VOCAB)   // 12,800,000

// Input element counts (for defensive identification)
#define SZ_FM   (N_IMG * C_DIM * HW)      // 1,048,576
#define SZ_AF   (N_DB * C_DIM)            // 204,800,000
#define SZ_REP  (N_DB * L_REP)            // 40,000,000

// -------- device scratch (no allocations allowed) --------
__device__ float               g_features[N_IMG * C_DIM];   // exact maxpooled
__device__ float               g_ftf32[N_IMG * C_DIM];      // tf32-rounded copy
__device__ float               g_x2[N_IMG];
__device__ unsigned int        g_minbits[N_IMG];
__device__ float               g_blockmin[N_IMG * NBLK];    // per-(row,block) min
__device__ unsigned long long  g_winner[N_IMG];

// -------- helpers --------
__device__ __forceinline__ float to_tf32(float x) {
    float r;
    asm("cvt.rna.tf32.f32 %0, %1;" : "=f"(r) : "f"(x));
    return r;
}

// ============================================================
// K0: max-pool over H*W. One warp per (b,c) pair; writes both the
// exact feature and its tf32-rounded copy.
// ============================================================
__global__ void k_maxpool(const float* __restrict__ fm) {
    int warp = (blockIdx.x * blockDim.x + threadIdx.x) >> 5;
    int lane = threadIdx.x & 31;
    if (warp >= N_IMG * C_DIM) return;
    const float* p = fm + (long long)warp * HW;
    float v = fmaxf(p[lane], p[lane + 32]);
    #pragma unroll
    for (int o = 16; o; o >>= 1) v = fmaxf(v, __shfl_xor_sync(0xFFFFFFFFu, v, o));
    if (lane == 0) {
        g_features[warp] = v;
        g_ftf32[warp]    = to_tf32(v);
    }
}

// ============================================================
// K0b: x2 per image row (one block per row, deterministic fixed-
// tree reduction) + scratch resets in block 0.
// ============================================================
__global__ void k_prep() {
    int b   = blockIdx.x;          // image row
    int tid = threadIdx.x;         // 256

    if (b == 0 && tid < N_IMG) {
        g_minbits[tid] = 0x7f800000u;                       // +inf bits
        g_winner[tid]  = 0xFFFFFFFFFFFFFFFFull;
    }

    const float* f = g_features + b * C_DIM;
    float v0 = f[tid], v1 = f[tid + 256];
    float s = v0 * v0 + v1 * v1;
    #pragma unroll
    for (int o = 16; o; o >>= 1) s += __shfl_xor_sync(0xFFFFFFFFu, s, o);
    __shared__ float sw[8];
    if ((tid & 31) == 0) sw[tid >> 5] = s;
    __syncthreads();
    if (tid == 0) {
        float t = 0.f;
        #pragma unroll
        for (int w = 0; w < 8; w++) t += sw[w];
        g_x2[b] = t;
    }
}

// ============================================================
// K1: fused GEMM + distances + per-row/per-block min.
// 256 threads (8 warps), 2 CTAs/SM. One barrier per K-chunk: the
// prefetch for chunk kc+1 is issued AFTER the barrier of chunk kc,
// at which point all threads have finished reading the buffer it
// overwrites (consumed in iteration kc-1). Exactly one cp.async
// group is pending at each wait -> wait_group 0 throughout.
// ============================================================
#define A_STRIDE (N_IMG * BPITCH)              // 1152 floats per A buffer
#define B_STRIDE (TN * BPITCH)                 // 9216 floats per B buffer
#define SMEM_FLOATS (2 * B_STRIDE + 2 * A_STRIDE + TN + N_IMG)
#define SMEM_BYTES  (SMEM_FLOATS * 4)          // 84,096 bytes

__device__ __forceinline__ void load_chunkA(const float* __restrict__ gA,
                                            float* dst, int kc, int tid) {
    int row = tid >> 3;              // 0..31
    int cg  = (tid & 7) * 4;         // float4 slot
    unsigned saddr = (unsigned)__cvta_generic_to_shared(dst + row * BPITCH + cg);
    const float* g = gA + row * C_DIM + kc * KC + cg;
    asm volatile("cp.async.cg.shared.global [%0], [%1], 16;\n"
                 :: "r"(saddr), "l"(g));
}

__device__ __forceinline__ void load_chunkB(const float* __restrict__ af,
                                            long long j0, float* dst,
                                            int kc, int tid) {
    const float* src = af + j0 * C_DIM + kc * KC;
    int lf = (tid & 7) * 4;
    int rbase = tid >> 3;
    #pragma unroll
    for (int i = 0; i < 8; i++) {
        int r = rbase + i * 32;
        unsigned saddr = (unsigned)__cvta_generic_to_shared(dst + r * BPITCH + lf);
        bool ok = (j0 + r < N_DB);
        const float* g = ok ? (src + (long long)r * C_DIM + lf) : af;
        int sz = ok ? 16 : 0;                 // zero-fill OOB rows
        asm volatile("cp.async.cg.shared.global [%0], [%1], 16, %2;\n"
                     :: "r"(saddr), "l"(g), "r"(sz));
    }
    asm volatile("cp.async.commit_group;\n");
}

extern "C" __global__ void __launch_bounds__(256, 2)
k_main(const float* __restrict__ af, float* __restrict__ dist) {
    extern __shared__ float smem[];
    float*    sB   = smem;                           // 2 x 256 x 36
    float*    sAc  = sB + 2 * B_STRIDE;              // 2 x 32 x 36
    float*    sy2  = sAc + 2 * A_STRIDE;             // 256
    unsigned* smin = (unsigned*)(sy2 + TN);          // 32

    int tid  = threadIdx.x;
    int lane = tid & 31;
    int warp = tid >> 5;
    long long j0 = (long long)blockIdx.x * TN;

    if (tid < N_IMG) smin[tid] = 0x7f800000u;

    float c[2][4][4];
    #pragma unroll
    for (int t = 0; t < 2; t++)
        #pragma unroll
        for (int u = 0; u < 4; u++)
            #pragma unroll
            for (int q = 0; q < 4; q++) c[t][u][q] = 0.f;

    float y2acc = 0.f;

    // group 0: chunk 0 (A + B)
    load_chunkA(g_ftf32, sAc, 0, tid);
    load_chunkB(af, j0, sB, 0, tid);     // commit

    const int NCHUNK = C_DIM / KC;       // 16
    for (int kc = 0; kc < NCHUNK; kc++) {
        int cur = kc & 1;

        asm volatile("cp.async.wait_group 0;\n");   // only group kc pending
        __syncthreads();   // fresh buffer readable; old buffer fully consumed

        if (kc + 1 < NCHUNK) {
            // overwrites buffer (kc+1)&1, consumed in iteration kc-1 —
            // the barrier above guarantees all threads are past those reads.
            load_chunkA(g_ftf32, sAc + (cur ^ 1) * A_STRIDE, kc + 1, tid);
            load_chunkB(af, j0, sB + (cur ^ 1) * B_STRIDE, kc + 1, tid);
        }

        float* B = sB + cur * B_STRIDE;
        float* A = sAc + cur * A_STRIDE;

        // y2 accumulation: thread tid owns candidate row tid.
        {
            const float4* rp = (const float4*)(B + tid * BPITCH);
            #pragma unroll
            for (int i = 0; i < 8; i++) {
                float4 v = rp[i];
                y2acc += v.x * v.x + v.y * v.y + v.z * v.z + v.w * v.w;
            }
        }

        // tf32 MMA over this K-chunk (4 k-steps of 8)
        #pragma unroll
        for (int ks = 0; ks < 4; ks++) {
            float a[2][4];
            #pragma unroll
            for (int t = 0; t < 2; t++) {
                // addr ≡ lane (mod 32): conflict-free
                const float* Ap = A + (t * 16 + (lane >> 2)) * BPITCH
                                  + ks * 8 + (lane & 3);
                a[t][0] = Ap[0];
                a[t][1] = Ap[8 * BPITCH];
                a[t][2] = Ap[4];
                a[t][3] = Ap[8 * BPITCH + 4];
            }
            #pragma unroll
            for (int u = 0; u < 4; u++) {
                const float* Bp = B + (warp * 32 + u * 8 + (lane >> 2)) * BPITCH
                                  + ks * 8 + (lane & 3);
                float b0 = to_tf32(Bp[0]);
                float b1 = to_tf32(Bp[4]);
                #pragma unroll
                for (int t = 0; t < 2; t++) {
                    asm volatile(
                        "mma.sync.aligned.m16n8k8.row.col.f32.tf32.tf32.f32 "
                        "{%0,%1,%2,%3},{%4,%5,%6,%7},{%8,%9},{%0,%1,%2,%3};\n"
                        : "+f"(c[t][u][0]), "+f"(c[t][u][1]),
                          "+f"(c[t][u][2]), "+f"(c[t][u][3])
                        : "r"(__float_as_uint(a[t][0])), "r"(__float_as_uint(a[t][1])),
                          "r"(__float_as_uint(a[t][2])), "r"(__float_as_uint(a[t][3])),
                          "r"(__float_as_uint(b0)),      "r"(__float_as_uint(b1)));
                }
            }
        }
    }

    __syncthreads();       // all reads of final buffer done before sy2 write
    sy2[tid] = y2acc;
    __syncthreads();

    // epilogue: S = x2 + y2 - 2*xy, d = sqrt(max(S,0)); .cs float2 store + min
    #pragma unroll
    for (int t = 0; t < 2; t++) {
        #pragma unroll
        for (int p = 0; p < 2; p++) {
            int m = t * 16 + p * 8 + (lane >> 2);
            float x2v = g_x2[m];
            float dm = __uint_as_float(0x7f800000u);
            #pragma unroll
            for (int u = 0; u < 4; u++) {
                int jl = warp * 32 + u * 8 + (lane & 3) * 2;
                long long j = j0 + jl;
                float S0 = x2v + sy2[jl + 0] - 2.f * c[t][u][p * 2 + 0];
                float S1 = x2v + sy2[jl + 1] - 2.f * c[t][u][p * 2 + 1];
                float d0 = sqrtf(fmaxf(S0, 0.f));
                float d1 = sqrtf(fmaxf(S1, 0.f));
                if (j + 1 < N_DB) {
                    __stcs((float2*)(dist + (long long)m * N_DB + j),
                           make_float2(d0, d1));
                    dm = fminf(dm, fminf(d0, d1));
                } else if (j < N_DB) {
                    __stcs(dist + (long long)m * N_DB + j, d0);
                    dm = fminf(dm, d0);
                }
            }
            atomicMin(&smin[m], __float_as_uint(dm));
        }
    }
    __syncthreads();
    if (tid < N_IMG) {
        g_blockmin[tid * NBLK + blockIdx.x] = __uint_as_float(smin[tid]);
        atomicMin(&g_minbits[tid], smin[tid]);
    }
}

// ============================================================
// K2: fused candidate scan + exact argmin. One block (256 thr) per
// image row. Phase 1: flagged-block list from block minima
// (capacity NBLK: overflow impossible). Per flagged block:
// cooperative dist test (capacity TN: overflow impossible), then
// exact fp32 recompute + atomicMin (S_bits<<32)|j.
// Key order == (smallest S, then smallest j) == jnp.argmin.
// ============================================================
__global__ void k_cand_exact(const float* __restrict__ dist,
                             const float* __restrict__ af) {
    int m   = blockIdx.x;
    int tid = threadIdx.x;   // 256
    float thr = __uint_as_float(g_minbits[m]) + EPS_D;
    const float* row = dist + (long long)m * N_DB;
    const float* f   = g_features + m * C_DIM;

    __shared__ int   s_blocks[NBLK];
    __shared__ int   s_nb;
    __shared__ int   s_cand[TN];
    __shared__ int   s_nc;
    __shared__ float s_red[16];

    if (tid == 0) s_nb = 0;
    __syncthreads();

    for (int b = tid; b < NBLK; b += 256)
        if (g_blockmin[m * NBLK + b] <= thr)
            s_blocks[atomicAdd(&s_nb, 1)] = b;
    __syncthreads();

    int nb = s_nb;
    float x2v = g_x2[m];

    for (int i = 0; i < nb; i++) {
        if (tid == 0) s_nc = 0;
        __syncthreads();

        int j = s_blocks[i] * TN + tid;
        if (j < N_DB && row[j] <= thr)
            s_cand[atomicAdd(&s_nc, 1)] = j;
        __syncthreads();

        int nc = s_nc;
        for (int c = 0; c < nc; c++) {
            int jj = s_cand[c];
            const float* a = af + (long long)jj * C_DIM;
            float a0 = a[tid], a1 = a[tid + 256];
            float dotp = f[tid] * a0 + f[tid + 256] * a1;
            float y2p  = a0 * a0 + a1 * a1;
            #pragma unroll
            for (int o = 16; o; o >>= 1) {
                dotp += __shfl_xor_sync(0xFFFFFFFFu, dotp, o);
                y2p  += __shfl_xor_sync(0xFFFFFFFFu, y2p, o);
            }
            if ((tid & 31) == 0) {
                s_red[tid >> 5]       = dotp;   // warps 0..7
                s_red[8 + (tid >> 5)] = y2p;
            }
            __syncthreads();
            if (tid == 0) {
                float D = 0.f, Y = 0.f;
                #pragma unroll
                for (int w = 0; w < 8; w++) { D += s_red[w]; Y += s_red[8 + w]; }
                float S = fmaxf(x2v + Y - 2.f * D, 0.f);
                unsigned long long key =
                    ((unsigned long long)__float_as_uint(S) << 32) | (unsigned)jj;
                atomicMin(&g_winner[m], key);
            }
            __syncthreads();   // protect s_red reuse
        }
        __syncthreads();       // protect s_nc reset
    }
}

// ============================================================
// K3: fused one-hot fill (zero + scatter; output arrives poisoned).
// One block per (b,t) row of 5000 floats. Branch-free parallel
// int64/int32 detection (threads 0..63 probe odd words, atomicOr).
// .cs streaming stores: write-once data, keep it out of L2.
// ============================================================
__global__ void k_onehot(const void* __restrict__ rep, float* __restrict__ oh) {
    int idx = blockIdx.x;              // 0 .. N_IMG*T_OUT-1
    int b = idx / T_OUT, t = idx - b * T_OUT;
    int tid = threadIdx.x;

    __shared__ int s_acc;
    __shared__ unsigned s_w;
    if (tid == 0) {
        s_acc = 0;
        s_w = (unsigned)(g_winner[b] & 0xFFFFFFFFu);
    }
    __syncthreads();
    if (tid < 64) {
        int odd = ((const int*)rep)[2 * tid + 1];
        if (odd != 0) atomicOr(&s_acc, 1);
    }
    __syncthreads();

    int is64 = (s_acc == 0);
    long long off = (long long)s_w * L_REP + t;
    int v = is64 ? (int)((const long long*)rep)[off]
                 : ((const int*)rep)[off];

    float4* row = (float4*)(oh + (long long)idx * VOCAB);   // 1250 float4
    const float4 z = make_float4(0.f, 0.f, 0.f, 0.f);
    int slot = v >> 2;
    for (int i = tid; i < VOCAB / 4; i += blockDim.x) {
        float4 out = z;
        if (i == slot) ((float*)&out)[v & 3] = 1.0f;
        __stcs(&row[i], out);
    }
}

// ============================================================
// Launch
// ============================================================
extern "C" void kernel_launch(void* const* d_in, const int* in_sizes, int n_in,
                              void* d_out, int out_size) {
    // Defensive binding: identify tensors by element count (all distinct).
    const float* fm  = nullptr;   // feature_maps (32,512,8,8)
    const float* af  = nullptr;   // all_features (400000,512)
    const void*  rep = nullptr;   // all_reports  (400000,100)
    for (int i = 0; i < n_in; i++) {
        if      (in_sizes[i] == SZ_FM)  fm  = (const float*)d_in[i];
        else if (in_sizes[i] == SZ_AF)  af  = (const float*)d_in[i];
        else if (in_sizes[i] == SZ_REP) rep = d_in[i];
    }
    if (!fm)  fm  = (const float*)d_in[0];
    if (!af)  af  = (const float*)d_in[1];
    if (!rep) rep = d_in[2];

    float* oh   = (float*)d_out;                          // one_hot first
    float* dist = (float*)d_out + ONE_HOT_ELEMS;          // distances second

    cudaFuncSetAttribute(k_main, cudaFuncAttributeMaxDynamicSharedMemorySize,
                         SMEM_BYTES);

    k_maxpool<<<(N_IMG * C_DIM) / 4, 128>>>(fm);
    k_prep<<<N_IMG, 256>>>();

    k_main<<<NBLK, 256, SMEM_BYTES>>>(af, dist);

    k_cand_exact<<<N_IMG, 256>>>(dist, af);
    k_onehot<<<N_IMG * T_OUT, 256>>>(rep, oh);
}